// round 1
// baseline (speedup 1.0000x reference)
#include <cuda_runtime.h>
#include <math.h>

// Problem constants
constexpr int kS    = 1024;
constexpr int kD    = 768;
constexpr int kL    = 12;
constexpr int kH    = 24;
constexpr int kQKV  = 2304;   // H*(32+32+32)
constexpr int kFF   = 1536;   // 2*D
constexpr int kV    = 50304;

// Scratch (device globals; no allocation allowed)
__device__ float g_x  [kS * kD];
__device__ float g_xn [kS * kD];
__device__ float g_h  [kS * kFF];   // pos hidden / FF z buffer
__device__ float g_y  [kS * kQKV];  // qkv
__device__ float g_att[kS * kD];
__device__ float g_g  [kS * kD];    // GLU out

// ---------------------------------------------------------------- embed gather
__global__ void embed_kernel(const int* __restrict__ tok,
                             const float* __restrict__ ew,
                             float* __restrict__ x) {
    int idx = blockIdx.x * blockDim.x + threadIdx.x;
    if (idx < kS * kD) {
        int t = idx / kD, d = idx - t * kD;
        x[idx] = ew[(size_t)tok[t] * kD + d];
    }
}

// ---------------------------------------------------------------- layernorm
__global__ void ln_kernel(const float* __restrict__ x,
                          const float* __restrict__ gw,
                          const float* __restrict__ bw,
                          float* __restrict__ out) {
    int row = blockIdx.x;
    int tid = threadIdx.x;  // 256
    const float* xr = x + (size_t)row * kD;
    float v0 = xr[tid], v1 = xr[tid + 256], v2 = xr[tid + 512];
    float s = v0 + v1 + v2;
    __shared__ float red[8];
    unsigned lane = tid & 31, wid = tid >> 5;
    #pragma unroll
    for (int o = 16; o > 0; o >>= 1) s += __shfl_down_sync(0xffffffffu, s, o);
    if (lane == 0) red[wid] = s;
    __syncthreads();
    float tot = 0.f;
    #pragma unroll
    for (int i = 0; i < 8; i++) tot += red[i];
    float m = tot * (1.f / 768.f);
    float d0 = v0 - m, d1 = v1 - m, d2 = v2 - m;
    float s2 = d0 * d0 + d1 * d1 + d2 * d2;
    __syncthreads();
    #pragma unroll
    for (int o = 16; o > 0; o >>= 1) s2 += __shfl_down_sync(0xffffffffu, s2, o);
    if (lane == 0) red[wid] = s2;
    __syncthreads();
    float tot2 = 0.f;
    #pragma unroll
    for (int i = 0; i < 8; i++) tot2 += red[i];
    float scale = rsqrtf(tot2 * (1.f / 768.f) + 1e-5f);
    float* orow = out + (size_t)row * kD;
    orow[tid]       = d0 * scale * gw[tid]       + bw[tid];
    orow[tid + 256] = d1 * scale * gw[tid + 256] + bw[tid + 256];
    orow[tid + 512] = d2 * scale * gw[tid + 512] + bw[tid + 512];
}

// ---------------------------------------------------------------- pos scan (log space)
// a[t] = sum_{i<=t} log_sigmoid(h[i,d]);  Lv = logaddexp over (logit - a)
// x[t,d] += a[t] + Lv[t]
__global__ void pos_scan_kernel(const float* __restrict__ h, float* __restrict__ x) {
    int d = blockIdx.x * blockDim.x + threadIdx.x;
    if (d >= kD) return;
    float a = 0.f, Lv = 0.f;  // Lv = logsumexp, starts with element value 0
    for (int t = 0; t < kS; t++) {
        float hc = h[(size_t)t * kFF + d];
        float hl = h[(size_t)t * kFF + kD + d];
        float lc = fminf(hc, 0.f) - log1pf(__expf(-fabsf(hc)));  // log_sigmoid
        a += lc;
        float v = hl - a;
        float mx = fmaxf(Lv, v), mn = fminf(Lv, v);
        Lv = mx + log1pf(__expf(mn - mx));
        x[(size_t)t * kD + d] += a + Lv;
    }
}

// ---------------------------------------------------------------- GLU
__global__ void glu_kernel(const float* __restrict__ z, float* __restrict__ g) {
    int idx = blockIdx.x * blockDim.x + threadIdx.x;
    if (idx < kS * kD) {
        int t = idx / kD, d = idx - t * kD;
        float a = z[(size_t)t * kFF + d];
        float b = z[(size_t)t * kFF + kD + d];
        g[idx] = a / (1.f + __expf(-b));
    }
}

// ---------------------------------------------------------------- tiled SGEMM
// C[M,N] = A[M,K] @ op(B) (+bias) (+addsrc).  TRANSB: B is [N,K] row-major.
// BM=BN=64, BK=16, 256 threads, 4x4 microtile.
template <bool TRANSB>
__global__ void __launch_bounds__(256)
gemm_kernel(const float* __restrict__ A, const float* __restrict__ B,
            const float* __restrict__ bias, const float* __restrict__ addsrc,
            float* __restrict__ C, int M, int N, int K) {
    __shared__ float As[16][64];
    __shared__ float Bs[16][64];
    int tid = threadIdx.x;
    int tx = tid & 15, ty = tid >> 4;
    int n0 = blockIdx.x * 64, m0 = blockIdx.y * 64;

    float acc[4][4] = {};

    int am = tid >> 2;           // 0..63
    int ak = (tid & 3) * 4;      // 0,4,8,12
    const float* Aptr = A + (size_t)(m0 + am) * K + ak;

    for (int k0 = 0; k0 < K; k0 += 16) {
        float4 av = *(const float4*)(Aptr + k0);
        As[ak + 0][am] = av.x; As[ak + 1][am] = av.y;
        As[ak + 2][am] = av.z; As[ak + 3][am] = av.w;
        if (TRANSB) {
            int bn = tid >> 2;
            int bk = (tid & 3) * 4;
            float4 bv = *(const float4*)(B + (size_t)(n0 + bn) * K + k0 + bk);
            Bs[bk + 0][bn] = bv.x; Bs[bk + 1][bn] = bv.y;
            Bs[bk + 2][bn] = bv.z; Bs[bk + 3][bn] = bv.w;
        } else {
            int bk = tid >> 4;
            int bn = (tid & 15) * 4;
            float4 bv = *(const float4*)(B + (size_t)(k0 + bk) * N + n0 + bn);
            *(float4*)&Bs[bk][bn] = bv;
        }
        __syncthreads();
        #pragma unroll
        for (int kk = 0; kk < 16; kk++) {
            float4 a4 = *(float4*)&As[kk][ty * 4];
            float4 b4 = *(float4*)&Bs[kk][tx * 4];
            float ar[4] = {a4.x, a4.y, a4.z, a4.w};
            float br[4] = {b4.x, b4.y, b4.z, b4.w};
            #pragma unroll
            for (int i = 0; i < 4; i++)
                #pragma unroll
                for (int j = 0; j < 4; j++)
                    acc[i][j] += ar[i] * br[j];
        }
        __syncthreads();
    }

    // Epilogue: float4 stores
    #pragma unroll
    for (int i = 0; i < 4; i++) {
        int row = m0 + ty * 4 + i;
        size_t off = (size_t)row * N + n0 + tx * 4;
        float4 o = {acc[i][0], acc[i][1], acc[i][2], acc[i][3]};
        if (bias) {
            const float4 b4 = *(const float4*)(bias + n0 + tx * 4);
            o.x += b4.x; o.y += b4.y; o.z += b4.z; o.w += b4.w;
        }
        if (addsrc) {
            const float4 s4 = *(const float4*)(addsrc + off);
            o.x += s4.x; o.y += s4.y; o.z += s4.z; o.w += s4.w;
        }
        *(float4*)(C + off) = o;
    }
}

// ---------------------------------------------------------------- attention
// For head h, query tile of 64: P = causal(eQ @ eK^T); S += P@eV; Z += rowsum(P)
// att = log(S) - log(Z).  y layout per row: [h*96 : q(32) k(32) v(32)]
__global__ void __launch_bounds__(256)
attn_kernel(const float* __restrict__ y, float* __restrict__ att) {
    __shared__ float sQ[32][64];   // [i][q] exp(Q)
    __shared__ float sK[32][64];   // [i][k] exp(K)
    __shared__ float sV[64][32];   // [k][j] exp(V)
    __shared__ float sP[64][65];
    __shared__ float sZ[64];

    int h  = blockIdx.y;
    int qt = blockIdx.x;
    int t0 = qt * 64;
    int tid = threadIdx.x;

    int i4 = (tid & 7) * 4;   // 0..28
    int rr = tid >> 3;        // 0..31

    // Load eQ (transposed into smem)
    #pragma unroll
    for (int rep = 0; rep < 2; rep++) {
        int q = rr + rep * 32;
        float4 v = *(const float4*)(y + (size_t)(t0 + q) * kQKV + h * 96 + i4);
        sQ[i4 + 0][q] = __expf(v.x); sQ[i4 + 1][q] = __expf(v.y);
        sQ[i4 + 2][q] = __expf(v.z); sQ[i4 + 3][q] = __expf(v.w);
    }

    float Sacc[2][4] = {};
    float Zacc[2] = {};
    int tk = tid & 15, tq = tid >> 4;   // P phase: 4q x 4k per thread
    int vx = tid & 7,  ry = tid >> 3;   // S phase: rows ry*2, ry*2+1; cols vx*4

    for (int kt = 0; kt <= qt; kt++) {
        int s0 = kt * 64;
        __syncthreads();
        // Load eK (transposed), eV
        #pragma unroll
        for (int rep = 0; rep < 2; rep++) {
            int k = rr + rep * 32;
            const float* base = y + (size_t)(s0 + k) * kQKV + h * 96;
            float4 kv = *(const float4*)(base + 32 + i4);
            sK[i4 + 0][k] = __expf(kv.x); sK[i4 + 1][k] = __expf(kv.y);
            sK[i4 + 2][k] = __expf(kv.z); sK[i4 + 3][k] = __expf(kv.w);
            float4 vv = *(const float4*)(base + 64 + i4);
            float4 ev = {__expf(vv.x), __expf(vv.y), __expf(vv.z), __expf(vv.w)};
            *(float4*)&sV[k][i4] = ev;
        }
        __syncthreads();
        // P = eQ^T-tile @ eK-tile  (each thread: 4x4)
        float p[4][4] = {};
        #pragma unroll
        for (int i = 0; i < 32; i++) {
            float4 a4 = *(float4*)&sQ[i][tq * 4];
            float4 b4 = *(float4*)&sK[i][tk * 4];
            float ar[4] = {a4.x, a4.y, a4.z, a4.w};
            float br[4] = {b4.x, b4.y, b4.z, b4.w};
            #pragma unroll
            for (int r = 0; r < 4; r++)
                #pragma unroll
                for (int c = 0; c < 4; c++)
                    p[r][c] += ar[r] * br[c];
        }
        if (kt == qt) {  // causal mask within diagonal tile
            #pragma unroll
            for (int r = 0; r < 4; r++)
                #pragma unroll
                for (int c = 0; c < 4; c++)
                    if (tk * 4 + c > tq * 4 + r) p[r][c] = 0.f;
        }
        #pragma unroll
        for (int r = 0; r < 4; r++)
            #pragma unroll
            for (int c = 0; c < 4; c++)
                sP[tq * 4 + r][tk * 4 + c] = p[r][c];
        __syncthreads();
        // S += P @ eV ; Z += rowsum(P)
        #pragma unroll 8
        for (int k = 0; k < 64; k++) {
            float p0 = sP[ry * 2 + 0][k];
            float p1 = sP[ry * 2 + 1][k];
            float4 vv = *(float4*)&sV[k][vx * 4];
            Sacc[0][0] += p0 * vv.x; Sacc[0][1] += p0 * vv.y;
            Sacc[0][2] += p0 * vv.z; Sacc[0][3] += p0 * vv.w;
            Sacc[1][0] += p1 * vv.x; Sacc[1][1] += p1 * vv.y;
            Sacc[1][2] += p1 * vv.z; Sacc[1][3] += p1 * vv.w;
            if (vx == 0) { Zacc[0] += p0; Zacc[1] += p1; }
        }
    }
    if (vx == 0) { sZ[ry * 2] = Zacc[0]; sZ[ry * 2 + 1] = Zacc[1]; }
    __syncthreads();
    #pragma unroll
    for (int r = 0; r < 2; r++) {
        int row = t0 + ry * 2 + r;
        float lz = __logf(sZ[ry * 2 + r]);
        float4 o;
        o.x = __logf(Sacc[r][0]) - lz;
        o.y = __logf(Sacc[r][1]) - lz;
        o.z = __logf(Sacc[r][2]) - lz;
        o.w = __logf(Sacc[r][3]) - lz;
        *(float4*)&att[(size_t)row * kD + h * 32 + vx * 4] = o;
    }
}

// ---------------------------------------------------------------- launch
extern "C" void kernel_launch(void* const* d_in, const int* in_sizes, int n_in,
                              void* d_out, int out_size) {
    const int*   tok     = (const int*)  d_in[0];
    const float* embed_w = (const float*)d_in[1];
    const float* pos_w   = (const float*)d_in[2];
    const float* pos_b   = (const float*)d_in[3];
    const float* ln1_g   = (const float*)d_in[4];
    const float* ln1_b   = (const float*)d_in[5];
    const float* qkv_w   = (const float*)d_in[6];
    const float* qkv_b   = (const float*)d_in[7];
    const float* ff_w1   = (const float*)d_in[8];
    const float* ff_b1   = (const float*)d_in[9];
    const float* ff_w2   = (const float*)d_in[10];
    const float* lnf_g   = (const float*)d_in[11];
    const float* lnf_b   = (const float*)d_in[12];
    float* out = (float*)d_out;

    float *x, *xn, *hbuf, *y, *att, *g;
    cudaGetSymbolAddress((void**)&x,    g_x);
    cudaGetSymbolAddress((void**)&xn,   g_xn);
    cudaGetSymbolAddress((void**)&hbuf, g_h);
    cudaGetSymbolAddress((void**)&y,    g_y);
    cudaGetSymbolAddress((void**)&att,  g_att);
    cudaGetSymbolAddress((void**)&g,    g_g);

    // 1. embedding
    embed_kernel<<<(kS * kD + 255) / 256, 256>>>(tok, embed_w, x);

    // 2. positional: h = x @ pos_w + pos_b ; scan ; x += rec
    gemm_kernel<false><<<dim3(kFF / 64, kS / 64), 256>>>(
        x, pos_w, pos_b, nullptr, hbuf, kS, kFF, kD);
    pos_scan_kernel<<<6, 128>>>(hbuf, x);

    // 3. layers
    for (int l = 0; l < kL; l++) {
        ln_kernel<<<kS, 256>>>(x, ln1_g + (size_t)l * kD, ln1_b + (size_t)l * kD, xn);
        gemm_kernel<false><<<dim3(kQKV / 64, kS / 64), 256>>>(
            xn, qkv_w + (size_t)l * kD * kQKV, qkv_b + (size_t)l * kQKV,
            nullptr, y, kS, kQKV, kD);
        attn_kernel<<<dim3(kS / 64, kH), 256>>>(y, att);
        gemm_kernel<false><<<dim3(kFF / 64, kS / 64), 256>>>(
            att, ff_w1 + (size_t)l * kD * kFF, ff_b1 + (size_t)l * kFF,
            nullptr, hbuf, kS, kFF, kD);
        glu_kernel<<<(kS * kD + 255) / 256, 256>>>(hbuf, g);
        gemm_kernel<false><<<dim3(kD / 64, kS / 64), 256>>>(
            g, ff_w2 + (size_t)l * kD * kD, nullptr, x, x, kS, kD, kD);
    }

    // 4. final LN + logits (NT gemm vs embed table)
    ln_kernel<<<kS, 256>>>(x, lnf_g, lnf_b, xn);
    gemm_kernel<true><<<dim3(kV / 64, kS / 64), 256>>>(
        xn, embed_w, nullptr, nullptr, out, kS, kV, kD);
}

// round 5
// speedup vs baseline: 1.8638x; 1.8638x over previous
#include <cuda_runtime.h>
#include <math.h>
#include <stdint.h>

// Problem constants
constexpr int kS    = 1024;
constexpr int kD    = 768;
constexpr int kL    = 12;
constexpr int kH    = 24;
constexpr int kQKV  = 2304;   // H*(32+32+32)
constexpr int kFF   = 1536;   // 2*D
constexpr int kV    = 50304;
constexpr int kK    = 768;    // shared GEMM K

// Scratch (device globals; no allocation allowed) — ~25 MB total
__device__ float g_x  [kS * kD];
__device__ float g_xn [kS * kD];
__device__ float g_h  [kS * kFF];   // pos hidden / FF z buffer
__device__ float g_y  [kS * kQKV];  // qkv
__device__ float g_att[kS * kD];
__device__ float g_g  [kS * kD];    // GLU out

// ================================================================ tf32 mma GEMM
// C[M,N] = A[M,K=768] @ op(B) (+bias) (+addsrc)
// TRANSB: B is [N,K] row-major (logits vs embed table).
// !TRANSB: B is [K,N] row-major (natural weight layout).
// BM=BN=128, BK=16, 256 threads (8 warps), warp tile 32x64.
// mma.sync.aligned.m16n8k8.row.col.f32.tf32.tf32.f32
constexpr int kPadA  = 20;    // A smem word stride (conflict-free frag loads)
constexpr int kPadBN = 136;   // B smem row stride for [k][n] layout (8*t4+g distinct mod 32)
constexpr int kNIter = kK / 16;  // 48

__device__ __forceinline__ uint32_t f2tf32(float f) {
    uint32_t u;
    asm("cvt.rna.tf32.f32 %0, %1;" : "=r"(u) : "f"(f));
    return u;
}

__device__ __forceinline__ void mma_tf32(float c[4],
                                         const uint32_t a[4],
                                         const uint32_t b[2]) {
    asm volatile(
        "mma.sync.aligned.m16n8k8.row.col.f32.tf32.tf32.f32 "
        "{%0,%1,%2,%3}, {%4,%5,%6,%7}, {%8,%9}, {%0,%1,%2,%3};"
        : "+f"(c[0]), "+f"(c[1]), "+f"(c[2]), "+f"(c[3])
        : "r"(a[0]), "r"(a[1]), "r"(a[2]), "r"(a[3]),
          "r"(b[0]), "r"(b[1]));
}

template <bool TRANSB>
__global__ void __launch_bounds__(256)
gemm_mma_kernel(const float* __restrict__ A, const float* __restrict__ B,
                const float* __restrict__ bias, const float* __restrict__ addsrc,
                float* __restrict__ C, int N) {
    constexpr int BSZ = TRANSB ? (128 * kPadA) : (16 * kPadBN);
    __shared__ uint32_t As[2][128 * kPadA];
    __shared__ uint32_t Bs[2][BSZ];

    int tid  = threadIdx.x;
    int lane = tid & 31;
    int w    = tid >> 5;
    int g    = lane >> 2;     // groupID
    int t4   = lane & 3;      // threadID_in_group
    int n0   = blockIdx.x * 128;
    int m0   = blockIdx.y * 128;
    int wm   = (w & 3) * 32;  // warp m offset
    int wn   = (w >> 2) * 64; // warp n offset

    // A staging mapping: rows srow, srow+64; k cols scol..scol+3
    int srow = tid >> 2;          // 0..63
    int scol = (tid & 3) * 4;     // 0,4,8,12
    const float* gA0 = A + (size_t)(m0 + srow) * kK + scol;
    const float* gA1 = A + (size_t)(m0 + srow + 64) * kK + scol;

    // B staging mapping
    const float* gB0;
    const float* gB1;
    int kr = tid >> 5;            // 0..7   (NN path)
    int c4 = (tid & 31) * 4;      // 0..124 (NN path)
    if (TRANSB) {
        gB0 = B + (size_t)(n0 + srow) * kK + scol;
        gB1 = B + (size_t)(n0 + srow + 64) * kK + scol;
    } else {
        gB0 = B + (size_t)kr * N + n0 + c4;
        gB1 = B + (size_t)(kr + 8) * N + n0 + c4;
    }

    float acc[2][8][4];
    #pragma unroll
    for (int f = 0; f < 2; f++)
        #pragma unroll
        for (int j = 0; j < 8; j++)
            #pragma unroll
            for (int q = 0; q < 4; q++) acc[f][j][q] = 0.f;

    auto ldgB = [&](int it, float4& rb0, float4& rb1) {
        if (TRANSB) {
            rb0 = *(const float4*)(gB0 + it * 16);
            rb1 = *(const float4*)(gB1 + it * 16);
        } else {
            rb0 = *(const float4*)(gB0 + (size_t)(it * 16) * N);
            rb1 = *(const float4*)(gB1 + (size_t)(it * 16) * N);
        }
    };

    auto sts = [&](int buf, float4 va0, float4 va1, float4 vb0, float4 vb1) {
        uint32_t* ap0 = &As[buf][srow * kPadA + scol];
        uint32_t* ap1 = &As[buf][(srow + 64) * kPadA + scol];
        uint4 ua0 = {f2tf32(va0.x), f2tf32(va0.y), f2tf32(va0.z), f2tf32(va0.w)};
        uint4 ua1 = {f2tf32(va1.x), f2tf32(va1.y), f2tf32(va1.z), f2tf32(va1.w)};
        *(uint4*)ap0 = ua0;
        *(uint4*)ap1 = ua1;
        uint4 ub0 = {f2tf32(vb0.x), f2tf32(vb0.y), f2tf32(vb0.z), f2tf32(vb0.w)};
        uint4 ub1 = {f2tf32(vb1.x), f2tf32(vb1.y), f2tf32(vb1.z), f2tf32(vb1.w)};
        if (TRANSB) {
            *(uint4*)&Bs[buf][srow * kPadA + scol] = ub0;
            *(uint4*)&Bs[buf][(srow + 64) * kPadA + scol] = ub1;
        } else {
            *(uint4*)&Bs[buf][kr * kPadBN + c4] = ub0;
            *(uint4*)&Bs[buf][(kr + 8) * kPadBN + c4] = ub1;
        }
    };

    // preload iter 0
    float4 ra0 = *(const float4*)(gA0);
    float4 ra1 = *(const float4*)(gA1);
    float4 rb0, rb1;
    ldgB(0, rb0, rb1);
    sts(0, ra0, ra1, rb0, rb1);
    __syncthreads();

    for (int it = 0; it < kNIter; it++) {
        int buf = it & 1;
        if (it + 1 < kNIter) {
            int k0 = (it + 1) * 16;
            ra0 = *(const float4*)(gA0 + k0);
            ra1 = *(const float4*)(gA1 + k0);
            ldgB(it + 1, rb0, rb1);
        }
        // compute 2 ksteps of 8
        #pragma unroll
        for (int ks = 0; ks < 2; ks++) {
            int kq = ks * 8 + t4;
            uint32_t a[2][4], b[8][2];
            #pragma unroll
            for (int f = 0; f < 2; f++) {
                int m = wm + f * 16 + g;
                a[f][0] = As[buf][m * kPadA + kq];
                a[f][1] = As[buf][(m + 8) * kPadA + kq];
                a[f][2] = As[buf][m * kPadA + kq + 4];
                a[f][3] = As[buf][(m + 8) * kPadA + kq + 4];
            }
            #pragma unroll
            for (int j = 0; j < 8; j++) {
                int n = wn + j * 8 + g;
                if (TRANSB) {
                    b[j][0] = Bs[buf][n * kPadA + kq];
                    b[j][1] = Bs[buf][n * kPadA + kq + 4];
                } else {
                    b[j][0] = Bs[buf][kq * kPadBN + n];
                    b[j][1] = Bs[buf][(kq + 4) * kPadBN + n];
                }
            }
            #pragma unroll
            for (int f = 0; f < 2; f++)
                #pragma unroll
                for (int j = 0; j < 8; j++)
                    mma_tf32(acc[f][j], a[f], b[j]);
        }
        if (it + 1 < kNIter) sts(buf ^ 1, ra0, ra1, rb0, rb1);
        __syncthreads();
    }

    // epilogue
    #pragma unroll
    for (int f = 0; f < 2; f++) {
        int r0 = m0 + wm + f * 16 + g;
        #pragma unroll
        for (int j = 0; j < 8; j++) {
            int n = n0 + wn + j * 8 + t4 * 2;
            float2 lo = {acc[f][j][0], acc[f][j][1]};
            float2 hi = {acc[f][j][2], acc[f][j][3]};
            if (bias) {
                float2 b2 = *(const float2*)(bias + n);
                lo.x += b2.x; lo.y += b2.y;
                hi.x += b2.x; hi.y += b2.y;
            }
            size_t o0 = (size_t)r0 * N + n;
            size_t o1 = (size_t)(r0 + 8) * N + n;
            if (addsrc) {
                float2 s0 = *(const float2*)(addsrc + o0);
                float2 s1 = *(const float2*)(addsrc + o1);
                lo.x += s0.x; lo.y += s0.y;
                hi.x += s1.x; hi.y += s1.y;
            }
            *(float2*)(C + o0) = lo;
            *(float2*)(C + o1) = hi;
        }
    }
}

// ================================================================ embed gather
__global__ void embed_kernel(const int* __restrict__ tok,
                             const float* __restrict__ ew,
                             float* __restrict__ x) {
    int idx = blockIdx.x * blockDim.x + threadIdx.x;
    if (idx < kS * kD) {
        int t = idx / kD, d = idx - t * kD;
        x[idx] = ew[(size_t)tok[t] * kD + d];
    }
}

// ================================================================ layernorm
__global__ void ln_kernel(const float* __restrict__ x,
                          const float* __restrict__ gw,
                          const float* __restrict__ bw,
                          float* __restrict__ out) {
    int row = blockIdx.x;
    int tid = threadIdx.x;  // 256
    const float* xr = x + (size_t)row * kD;
    float v0 = xr[tid], v1 = xr[tid + 256], v2 = xr[tid + 512];
    float s = v0 + v1 + v2;
    __shared__ float red[8];
    unsigned lane = tid & 31, wid = tid >> 5;
    #pragma unroll
    for (int o = 16; o > 0; o >>= 1) s += __shfl_down_sync(0xffffffffu, s, o);
    if (lane == 0) red[wid] = s;
    __syncthreads();
    float tot = 0.f;
    #pragma unroll
    for (int i = 0; i < 8; i++) tot += red[i];
    float m = tot * (1.f / 768.f);
    float d0 = v0 - m, d1 = v1 - m, d2 = v2 - m;
    float s2 = d0 * d0 + d1 * d1 + d2 * d2;
    __syncthreads();
    #pragma unroll
    for (int o = 16; o > 0; o >>= 1) s2 += __shfl_down_sync(0xffffffffu, s2, o);
    if (lane == 0) red[wid] = s2;
    __syncthreads();
    float tot2 = 0.f;
    #pragma unroll
    for (int i = 0; i < 8; i++) tot2 += red[i];
    float scale = rsqrtf(tot2 * (1.f / 768.f) + 1e-5f);
    float* orow = out + (size_t)row * kD;
    orow[tid]       = d0 * scale * gw[tid]       + bw[tid];
    orow[tid + 256] = d1 * scale * gw[tid + 256] + bw[tid + 256];
    orow[tid + 512] = d2 * scale * gw[tid + 512] + bw[tid + 512];
}

// ================================================================ pos scan
__global__ void pos_scan_kernel(const float* __restrict__ h, float* __restrict__ x) {
    int d = blockIdx.x * blockDim.x + threadIdx.x;
    if (d >= kD) return;
    float a = 0.f, Lv = 0.f;
    for (int t = 0; t < kS; t++) {
        float hc = h[(size_t)t * kFF + d];
        float hl = h[(size_t)t * kFF + kD + d];
        float lc = fminf(hc, 0.f) - log1pf(__expf(-fabsf(hc)));
        a += lc;
        float v = hl - a;
        float mx = fmaxf(Lv, v), mn = fminf(Lv, v);
        Lv = mx + log1pf(__expf(mn - mx));
        x[(size_t)t * kD + d] += a + Lv;
    }
}

// ================================================================ GLU
__global__ void glu_kernel(const float* __restrict__ z, float* __restrict__ g) {
    int idx = blockIdx.x * blockDim.x + threadIdx.x;
    if (idx < kS * kD) {
        int t = idx / kD, d = idx - t * kD;
        float a = z[(size_t)t * kFF + d];
        float b = z[(size_t)t * kFF + kD + d];
        g[idx] = a / (1.f + __expf(-b));
    }
}

// ================================================================ attention
__global__ void __launch_bounds__(256)
attn_kernel(const float* __restrict__ y, float* __restrict__ att) {
    __shared__ float sQ[32][64];
    __shared__ float sK[32][64];
    __shared__ float sV[64][32];
    __shared__ float sP[64][65];
    __shared__ float sZ[64];

    int h  = blockIdx.y;
    int qt = blockIdx.x;
    int t0 = qt * 64;
    int tid = threadIdx.x;

    int i4 = (tid & 7) * 4;
    int rr = tid >> 3;

    #pragma unroll
    for (int rep = 0; rep < 2; rep++) {
        int q = rr + rep * 32;
        float4 v = *(const float4*)(y + (size_t)(t0 + q) * kQKV + h * 96 + i4);
        sQ[i4 + 0][q] = __expf(v.x); sQ[i4 + 1][q] = __expf(v.y);
        sQ[i4 + 2][q] = __expf(v.z); sQ[i4 + 3][q] = __expf(v.w);
    }

    float Sacc[2][4] = {};
    float Zacc[2] = {};
    int tk = tid & 15, tq = tid >> 4;
    int vx = tid & 7,  ry = tid >> 3;

    for (int kt = 0; kt <= qt; kt++) {
        int s0 = kt * 64;
        __syncthreads();
        #pragma unroll
        for (int rep = 0; rep < 2; rep++) {
            int k = rr + rep * 32;
            const float* base = y + (size_t)(s0 + k) * kQKV + h * 96;
            float4 kv = *(const float4*)(base + 32 + i4);
            sK[i4 + 0][k] = __expf(kv.x); sK[i4 + 1][k] = __expf(kv.y);
            sK[i4 + 2][k] = __expf(kv.z); sK[i4 + 3][k] = __expf(kv.w);
            float4 vv = *(const float4*)(base + 64 + i4);
            float4 ev = {__expf(vv.x), __expf(vv.y), __expf(vv.z), __expf(vv.w)};
            *(float4*)&sV[k][i4] = ev;
        }
        __syncthreads();
        float p[4][4] = {};
        #pragma unroll
        for (int i = 0; i < 32; i++) {
            float4 a4 = *(float4*)&sQ[i][tq * 4];
            float4 b4 = *(float4*)&sK[i][tk * 4];
            float ar[4] = {a4.x, a4.y, a4.z, a4.w};
            float br[4] = {b4.x, b4.y, b4.z, b4.w};
            #pragma unroll
            for (int r = 0; r < 4; r++)
                #pragma unroll
                for (int c = 0; c < 4; c++)
                    p[r][c] += ar[r] * br[c];
        }
        if (kt == qt) {
            #pragma unroll
            for (int r = 0; r < 4; r++)
                #pragma unroll
                for (int c = 0; c < 4; c++)
                    if (tk * 4 + c > tq * 4 + r) p[r][c] = 0.f;
        }
        #pragma unroll
        for (int r = 0; r < 4; r++)
            #pragma unroll
            for (int c = 0; c < 4; c++)
                sP[tq * 4 + r][tk * 4 + c] = p[r][c];
        __syncthreads();
        #pragma unroll 8
        for (int k = 0; k < 64; k++) {
            float p0 = sP[ry * 2 + 0][k];
            float p1 = sP[ry * 2 + 1][k];
            float4 vv = *(float4*)&sV[k][vx * 4];
            Sacc[0][0] += p0 * vv.x; Sacc[0][1] += p0 * vv.y;
            Sacc[0][2] += p0 * vv.z; Sacc[0][3] += p0 * vv.w;
            Sacc[1][0] += p1 * vv.x; Sacc[1][1] += p1 * vv.y;
            Sacc[1][2] += p1 * vv.z; Sacc[1][3] += p1 * vv.w;
            if (vx == 0) { Zacc[0] += p0; Zacc[1] += p1; }
        }
    }
    if (vx == 0) { sZ[ry * 2] = Zacc[0]; sZ[ry * 2 + 1] = Zacc[1]; }
    __syncthreads();
    #pragma unroll
    for (int r = 0; r < 2; r++) {
        int row = t0 + ry * 2 + r;
        float lz = __logf(sZ[ry * 2 + r]);
        float4 o;
        o.x = __logf(Sacc[r][0]) - lz;
        o.y = __logf(Sacc[r][1]) - lz;
        o.z = __logf(Sacc[r][2]) - lz;
        o.w = __logf(Sacc[r][3]) - lz;
        *(float4*)&att[(size_t)row * kD + h * 32 + vx * 4] = o;
    }
}

// ================================================================ launch
extern "C" void kernel_launch(void* const* d_in, const int* in_sizes, int n_in,
                              void* d_out, int out_size) {
    const int*   tok     = (const int*)  d_in[0];
    const float* embed_w = (const float*)d_in[1];
    const float* pos_w   = (const float*)d_in[2];
    const float* pos_b   = (const float*)d_in[3];
    const float* ln1_g   = (const float*)d_in[4];
    const float* ln1_b   = (const float*)d_in[5];
    const float* qkv_w   = (const float*)d_in[6];
    const float* qkv_b   = (const float*)d_in[7];
    const float* ff_w1   = (const float*)d_in[8];
    const float* ff_b1   = (const float*)d_in[9];
    const float* ff_w2   = (const float*)d_in[10];
    const float* lnf_g   = (const float*)d_in[11];
    const float* lnf_b   = (const float*)d_in[12];
    float* out = (float*)d_out;

    float *x, *xn, *hbuf, *y, *att, *g;
    cudaGetSymbolAddress((void**)&x,    g_x);
    cudaGetSymbolAddress((void**)&xn,   g_xn);
    cudaGetSymbolAddress((void**)&hbuf, g_h);
    cudaGetSymbolAddress((void**)&y,    g_y);
    cudaGetSymbolAddress((void**)&att,  g_att);
    cudaGetSymbolAddress((void**)&g,    g_g);

    // 1. embedding
    embed_kernel<<<(kS * kD + 255) / 256, 256>>>(tok, embed_w, x);

    // 2. positional: h = x @ pos_w + pos_b ; scan ; x += rec
    gemm_mma_kernel<false><<<dim3(kFF / 128, kS / 128), 256>>>(
        x, pos_w, pos_b, nullptr, hbuf, kFF);
    pos_scan_kernel<<<6, 128>>>(hbuf, x);

    // 3. layers (weights used in natural [K,N] layout — no transposes)
    for (int l = 0; l < kL; l++) {
        ln_kernel<<<kS, 256>>>(x, ln1_g + (size_t)l * kD, ln1_b + (size_t)l * kD, xn);
        gemm_mma_kernel<false><<<dim3(kQKV / 128, kS / 128), 256>>>(
            xn, qkv_w + (size_t)l * kD * kQKV, qkv_b + (size_t)l * kQKV, nullptr, y, kQKV);
        attn_kernel<<<dim3(kS / 64, kH), 256>>>(y, att);
        gemm_mma_kernel<false><<<dim3(kFF / 128, kS / 128), 256>>>(
            att, ff_w1 + (size_t)l * kD * kFF, ff_b1 + (size_t)l * kFF, nullptr, hbuf, kFF);
        glu_kernel<<<(kS * kD + 255) / 256, 256>>>(hbuf, g);
        gemm_mma_kernel<false><<<dim3(kD / 128, kS / 128), 256>>>(
            g, ff_w2 + (size_t)l * kD * kD, nullptr, x, x, kD);
    }

    // 4. final LN + logits (embed_w is [V, K] row-major -> TRANSB path)
    ln_kernel<<<kS, 256>>>(x, lnf_g, lnf_b, xn);
    gemm_mma_kernel<true><<<dim3(kV / 128, kS / 128), 256>>>(
        xn, embed_w, nullptr, nullptr, out, kV);
}

// round 7
// speedup vs baseline: 2.4145x; 1.2955x over previous
#include <cuda_runtime.h>
#include <cuda_bf16.h>
#include <math.h>
#include <stdint.h>

// Problem constants
constexpr int kS    = 1024;
constexpr int kD    = 768;
constexpr int kL    = 12;
constexpr int kH    = 24;
constexpr int kQKV  = 2304;   // H*(32+32+32)
constexpr int kFF   = 1536;   // 2*D
constexpr int kV    = 50304;
constexpr int kK    = 768;    // shared GEMM K

// Scratch (device globals; no allocation allowed)
__device__ float g_x    [kS * kD];
__device__ float g_xn   [kS * kD];
__device__ float g_h    [kS * kFF];
__device__ float g_y    [kS * kQKV];
__device__ float g_att  [kS * kD];
__device__ float g_g    [kS * kD];
__device__ float g_state[kH * 16 * 32 * 32];  // per (head, tile) KV state
__device__ float g_zs   [kH * 16 * 32];       // per (head, tile) K sum

// ================================================================ bf16-split mma GEMM
// C[M,N] = A[M,K=768] @ op(B) (+bias) (+addsrc), fp32 in/out.
// Split x = hi + lo (bf16 each); C = Ahi*Bhi + Ahi*Blo + Alo*Bhi.
// BM=BN=128, BK=16, 256 threads (8 warps), warp tile 32x64.
// mma.sync.aligned.m16n8k16.row.col.f32.bf16.bf16.f32
constexpr int kPw    = 12;          // smem word stride (8 kpair words + 4 pad)
constexpr int kBufW  = 128 * kPw;   // words per buffer per array
constexpr int kNIter = kK / 16;     // 48
// dynamic smem word offsets
constexpr int SA_HI = 0;
constexpr int SA_LO = 2 * kBufW;
constexpr int SB_HI = 4 * kBufW;
constexpr int SB_LO = 6 * kBufW;
constexpr int kSmemBytes = 8 * kBufW * 4;   // 49152 (== default 48KB limit)

__device__ __forceinline__ uint32_t pack_split(float x, float y, float& lx, float& ly) {
    __nv_bfloat162 h = __floats2bfloat162_rn(x, y);
    lx = x - __bfloat162float(h.x);
    ly = y - __bfloat162float(h.y);
    return *reinterpret_cast<uint32_t*>(&h);
}
__device__ __forceinline__ uint32_t pack_bf2(float x, float y) {
    __nv_bfloat162 h = __floats2bfloat162_rn(x, y);
    return *reinterpret_cast<uint32_t*>(&h);
}

__device__ __forceinline__ void mma_bf16(float c[4],
                                         const uint32_t a[4],
                                         const uint32_t b[2]) {
    asm volatile(
        "mma.sync.aligned.m16n8k16.row.col.f32.bf16.bf16.f32 "
        "{%0,%1,%2,%3}, {%4,%5,%6,%7}, {%8,%9}, {%0,%1,%2,%3};"
        : "+f"(c[0]), "+f"(c[1]), "+f"(c[2]), "+f"(c[3])
        : "r"(a[0]), "r"(a[1]), "r"(a[2]), "r"(a[3]),
          "r"(b[0]), "r"(b[1]));
}

template <bool TRANSB>
__global__ void __launch_bounds__(256)
gemm_mma_kernel(const float* __restrict__ A, const float* __restrict__ B,
                const float* __restrict__ bias, const float* __restrict__ addsrc,
                float* __restrict__ C, int N) {
    extern __shared__ uint32_t sm[];

    int tid  = threadIdx.x;
    int lane = tid & 31;
    int w    = tid >> 5;
    int g    = lane >> 2;
    int t4   = lane & 3;
    int n0   = blockIdx.x * 128;
    int m0   = blockIdx.y * 128;
    int wm   = (w & 3) * 32;
    int wn   = (w >> 2) * 64;

    // A staging: rows srow, srow+64; k cols scol..scol+3 (float4)
    int srow = tid >> 2;
    int scol = (tid & 3) * 4;
    const float* gA0 = A + (size_t)(m0 + srow) * kK + scol;
    const float* gA1 = A + (size_t)(m0 + srow + 64) * kK + scol;

    // B staging
    const float* gBt0;  const float* gBt1;       // TRANSB
    const float* gBc = nullptr;                  // NN: column base
    int nn = tid & 127, hh = tid >> 7;
    if (TRANSB) {
        gBt0 = B + (size_t)(n0 + srow) * kK + scol;
        gBt1 = B + (size_t)(n0 + srow + 64) * kK + scol;
    } else {
        gBc = B + n0 + nn;
    }

    float acc[2][8][4];
    #pragma unroll
    for (int f = 0; f < 2; f++)
        #pragma unroll
        for (int j = 0; j < 8; j++)
            #pragma unroll
            for (int q = 0; q < 4; q++) acc[f][j][q] = 0.f;

    float4 ra0, ra1, rbt0, rbt1;
    float rbn[8];

    auto ldg = [&](int it) {
        int k0 = it * 16;
        ra0 = *(const float4*)(gA0 + k0);
        ra1 = *(const float4*)(gA1 + k0);
        if (TRANSB) {
            rbt0 = *(const float4*)(gBt0 + k0);
            rbt1 = *(const float4*)(gBt1 + k0);
        } else {
            #pragma unroll
            for (int u = 0; u < 8; u++)
                rbn[u] = gBc[(size_t)(k0 + hh * 8 + u) * N];
        }
    };

    auto sts = [&](int buf) {
        int bo = buf * kBufW;
        // A rows
        {
            float l0, l1, l2, l3;
            uint32_t h0 = pack_split(ra0.x, ra0.y, l0, l1);
            uint32_t h1 = pack_split(ra0.z, ra0.w, l2, l3);
            int o = bo + srow * kPw + scol / 2;
            sm[SA_HI + o] = h0; sm[SA_HI + o + 1] = h1;
            sm[SA_LO + o] = pack_bf2(l0, l1); sm[SA_LO + o + 1] = pack_bf2(l2, l3);
            h0 = pack_split(ra1.x, ra1.y, l0, l1);
            h1 = pack_split(ra1.z, ra1.w, l2, l3);
            o = bo + (srow + 64) * kPw + scol / 2;
            sm[SA_HI + o] = h0; sm[SA_HI + o + 1] = h1;
            sm[SA_LO + o] = pack_bf2(l0, l1); sm[SA_LO + o + 1] = pack_bf2(l2, l3);
        }
        if (TRANSB) {
            float l0, l1, l2, l3;
            uint32_t h0 = pack_split(rbt0.x, rbt0.y, l0, l1);
            uint32_t h1 = pack_split(rbt0.z, rbt0.w, l2, l3);
            int o = bo + srow * kPw + scol / 2;
            sm[SB_HI + o] = h0; sm[SB_HI + o + 1] = h1;
            sm[SB_LO + o] = pack_bf2(l0, l1); sm[SB_LO + o + 1] = pack_bf2(l2, l3);
            h0 = pack_split(rbt1.x, rbt1.y, l0, l1);
            h1 = pack_split(rbt1.z, rbt1.w, l2, l3);
            o = bo + (srow + 64) * kPw + scol / 2;
            sm[SB_HI + o] = h0; sm[SB_HI + o + 1] = h1;
            sm[SB_LO + o] = pack_bf2(l0, l1); sm[SB_LO + o + 1] = pack_bf2(l2, l3);
        } else {
            int o = bo + nn * kPw + hh * 4;
            #pragma unroll
            for (int u = 0; u < 4; u++) {
                float l0, l1;
                uint32_t h = pack_split(rbn[2 * u], rbn[2 * u + 1], l0, l1);
                sm[SB_HI + o + u] = h;
                sm[SB_LO + o + u] = pack_bf2(l0, l1);
            }
        }
    };

    ldg(0);
    sts(0);
    __syncthreads();

    for (int it = 0; it < kNIter; it++) {
        int buf = it & 1;
        int bo  = buf * kBufW;
        if (it + 1 < kNIter) ldg(it + 1);

        uint32_t ahi[2][4], alo[2][4], bhi[8][2], blo[8][2];
        #pragma unroll
        for (int f = 0; f < 2; f++) {
            int m = wm + f * 16 + g;
            int o0 = bo + m * kPw + t4;
            int o1 = bo + (m + 8) * kPw + t4;
            ahi[f][0] = sm[SA_HI + o0];     ahi[f][1] = sm[SA_HI + o1];
            ahi[f][2] = sm[SA_HI + o0 + 4]; ahi[f][3] = sm[SA_HI + o1 + 4];
            alo[f][0] = sm[SA_LO + o0];     alo[f][1] = sm[SA_LO + o1];
            alo[f][2] = sm[SA_LO + o0 + 4]; alo[f][3] = sm[SA_LO + o1 + 4];
        }
        #pragma unroll
        for (int j = 0; j < 8; j++) {
            int n = wn + j * 8 + g;
            int o = bo + n * kPw + t4;
            bhi[j][0] = sm[SB_HI + o]; bhi[j][1] = sm[SB_HI + o + 4];
            blo[j][0] = sm[SB_LO + o]; blo[j][1] = sm[SB_LO + o + 4];
        }
        #pragma unroll
        for (int f = 0; f < 2; f++)
            #pragma unroll
            for (int j = 0; j < 8; j++) {
                mma_bf16(acc[f][j], ahi[f], bhi[j]);
                mma_bf16(acc[f][j], ahi[f], blo[j]);
                mma_bf16(acc[f][j], alo[f], bhi[j]);
            }

        if (it + 1 < kNIter) sts(buf ^ 1);
        __syncthreads();
    }

    // epilogue
    #pragma unroll
    for (int f = 0; f < 2; f++) {
        int r0 = m0 + wm + f * 16 + g;
        #pragma unroll
        for (int j = 0; j < 8; j++) {
            int n = n0 + wn + j * 8 + t4 * 2;
            float2 lo = {acc[f][j][0], acc[f][j][1]};
            float2 hi = {acc[f][j][2], acc[f][j][3]};
            if (bias) {
                float2 b2 = *(const float2*)(bias + n);
                lo.x += b2.x; lo.y += b2.y;
                hi.x += b2.x; hi.y += b2.y;
            }
            size_t o0 = (size_t)r0 * N + n;
            size_t o1 = (size_t)(r0 + 8) * N + n;
            if (addsrc) {
                float2 s0 = *(const float2*)(addsrc + o0);
                float2 s1 = *(const float2*)(addsrc + o1);
                lo.x += s0.x; lo.y += s0.y;
                hi.x += s1.x; hi.y += s1.y;
            }
            *(float2*)(C + o0) = lo;
            *(float2*)(C + o1) = hi;
        }
    }
}

// ================================================================ embed gather
__global__ void embed_kernel(const int* __restrict__ tok,
                             const float* __restrict__ ew,
                             float* __restrict__ x) {
    int idx = blockIdx.x * blockDim.x + threadIdx.x;
    if (idx < kS * kD) {
        int t = idx / kD, d = idx - t * kD;
        x[idx] = ew[(size_t)tok[t] * kD + d];
    }
}

// ================================================================ layernorm
__global__ void ln_kernel(const float* __restrict__ x,
                          const float* __restrict__ gw,
                          const float* __restrict__ bw,
                          float* __restrict__ out) {
    int row = blockIdx.x;
    int tid = threadIdx.x;  // 256
    const float* xr = x + (size_t)row * kD;
    float v0 = xr[tid], v1 = xr[tid + 256], v2 = xr[tid + 512];
    float s = v0 + v1 + v2;
    __shared__ float red[8];
    unsigned lane = tid & 31, wid = tid >> 5;
    #pragma unroll
    for (int o = 16; o > 0; o >>= 1) s += __shfl_down_sync(0xffffffffu, s, o);
    if (lane == 0) red[wid] = s;
    __syncthreads();
    float tot = 0.f;
    #pragma unroll
    for (int i = 0; i < 8; i++) tot += red[i];
    float m = tot * (1.f / 768.f);
    float d0 = v0 - m, d1 = v1 - m, d2 = v2 - m;
    float s2 = d0 * d0 + d1 * d1 + d2 * d2;
    __syncthreads();
    #pragma unroll
    for (int o = 16; o > 0; o >>= 1) s2 += __shfl_down_sync(0xffffffffu, s2, o);
    if (lane == 0) red[wid] = s2;
    __syncthreads();
    float tot2 = 0.f;
    #pragma unroll
    for (int i = 0; i < 8; i++) tot2 += red[i];
    float scale = rsqrtf(tot2 * (1.f / 768.f) + 1e-5f);
    float* orow = out + (size_t)row * kD;
    orow[tid]       = d0 * scale * gw[tid]       + bw[tid];
    orow[tid + 256] = d1 * scale * gw[tid + 256] + bw[tid + 256];
    orow[tid + 512] = d2 * scale * gw[tid + 512] + bw[tid + 512];
}

// ================================================================ pos scan
__global__ void pos_scan_kernel(const float* __restrict__ h, float* __restrict__ x) {
    int d = blockIdx.x * blockDim.x + threadIdx.x;
    if (d >= kD) return;
    float a = 0.f, Lv = 0.f;
    for (int t = 0; t < kS; t++) {
        float hc = h[(size_t)t * kFF + d];
        float hl = h[(size_t)t * kFF + kD + d];
        float lc = fminf(hc, 0.f) - log1pf(__expf(-fabsf(hc)));
        a += lc;
        float v = hl - a;
        float mx = fmaxf(Lv, v), mn = fminf(Lv, v);
        Lv = mx + log1pf(__expf(mn - mx));
        x[(size_t)t * kD + d] += a + Lv;
    }
}

// ================================================================ GLU
__global__ void glu_kernel(const float* __restrict__ z, float* __restrict__ g) {
    int idx = blockIdx.x * blockDim.x + threadIdx.x;
    if (idx < kS * kD) {
        int t = idx / kD, d = idx - t * kD;
        float a = z[(size_t)t * kFF + d];
        float b = z[(size_t)t * kFF + kD + d];
        g[idx] = a / (1.f + __expf(-b));
    }
}

// ================================================================ chunked attention
// Kernel 1: per (tile, head) KV-state: St[i][j] = sum_s eK[s][i]*eV[s][j]; zs[i] = sum_s eK[s][i]
__global__ void __launch_bounds__(256)
attn_state_kernel(const float* __restrict__ y, float* __restrict__ state,
                  float* __restrict__ zs) {
    __shared__ float sK[64][36];
    __shared__ float sV[64][36];
    int t = blockIdx.x, h = blockIdx.y;
    int tid = threadIdx.x;
    int i4 = (tid & 7) * 4, rr = tid >> 3;
    #pragma unroll
    for (int rep = 0; rep < 2; rep++) {
        int s = rr + rep * 32;
        const float* base = y + (size_t)(t * 64 + s) * kQKV + h * 96;
        float4 kv = *(const float4*)(base + 32 + i4);
        float4 vv = *(const float4*)(base + 64 + i4);
        float4 ek = {__expf(kv.x), __expf(kv.y), __expf(kv.z), __expf(kv.w)};
        float4 ev = {__expf(vv.x), __expf(vv.y), __expf(vv.z), __expf(vv.w)};
        *(float4*)&sK[s][i4] = ek;
        *(float4*)&sV[s][i4] = ev;
    }
    __syncthreads();
    int i = tid >> 3, j0 = (tid & 7) * 4;
    float a0 = 0.f, a1 = 0.f, a2 = 0.f, a3 = 0.f;
    #pragma unroll 4
    for (int s = 0; s < 64; s++) {
        float k = sK[s][i];
        float4 v = *(float4*)&sV[s][j0];
        a0 += k * v.x; a1 += k * v.y; a2 += k * v.z; a3 += k * v.w;
    }
    float4 o = {a0, a1, a2, a3};
    *(float4*)&state[((size_t)(h * 16 + t) * 32 + i) * 32 + j0] = o;
    if (tid < 32) {
        float z = 0.f;
        #pragma unroll 4
        for (int s = 0; s < 64; s++) z += sK[s][tid];
        zs[(h * 16 + t) * 32 + tid] = z;
    }
}

// Kernel 2: exclusive prefix over 16 tiles per head (in place)
__global__ void __launch_bounds__(1024)
attn_prefix_kernel(float* __restrict__ state, float* __restrict__ zs) {
    int h = blockIdx.x;
    int idx = threadIdx.x;  // 0..1023
    float run = 0.f;
    for (int t = 0; t < 16; t++) {
        size_t o = (size_t)(h * 16 + t) * 1024 + idx;
        float v = state[o];
        state[o] = run;
        run += v;
    }
    if (idx < 32) {
        float rz = 0.f;
        for (int t = 0; t < 16; t++) {
            int o = (h * 16 + t) * 32 + idx;
            float v = zs[o];
            zs[o] = rz;
            rz += v;
        }
    }
}

// Kernel 3: per (qtile, head): att = log(P_diag@eV + eQ@St_prev) - log(P_diag.rowsum + eQ@z_prev)
__global__ void __launch_bounds__(256)
attn_out_kernel(const float* __restrict__ y, const float* __restrict__ state,
                const float* __restrict__ zs, float* __restrict__ att) {
    __shared__ float sQ[32][64];
    __shared__ float sK[32][64];
    __shared__ float sV[64][36];
    __shared__ float sSt[32][36];
    __shared__ float sZp[32];
    __shared__ float sP[64][65];
    __shared__ float sZ[64];

    int qt = blockIdx.x, h = blockIdx.y;
    int t0 = qt * 64;
    int tid = threadIdx.x;
    int i4 = (tid & 7) * 4, rr = tid >> 3;

    // load eQ, eK (transposed), eV
    #pragma unroll
    for (int rep = 0; rep < 2; rep++) {
        int s = rr + rep * 32;
        const float* base = y + (size_t)(t0 + s) * kQKV + h * 96;
        float4 qv = *(const float4*)(base + i4);
        sQ[i4 + 0][s] = __expf(qv.x); sQ[i4 + 1][s] = __expf(qv.y);
        sQ[i4 + 2][s] = __expf(qv.z); sQ[i4 + 3][s] = __expf(qv.w);
        float4 kv = *(const float4*)(base + 32 + i4);
        sK[i4 + 0][s] = __expf(kv.x); sK[i4 + 1][s] = __expf(kv.y);
        sK[i4 + 2][s] = __expf(kv.z); sK[i4 + 3][s] = __expf(kv.w);
        float4 vv = *(const float4*)(base + 64 + i4);
        float4 ev = {__expf(vv.x), __expf(vv.y), __expf(vv.z), __expf(vv.w)};
        *(float4*)&sV[s][i4] = ev;
    }
    // load state + z prefix
    {
        int i = tid >> 3, j0 = (tid & 7) * 4;
        float4 st = *(const float4*)&state[((size_t)(h * 16 + qt) * 32 + i) * 32 + j0];
        *(float4*)&sSt[i][j0] = st;
        if (tid < 32) sZp[tid] = zs[(h * 16 + qt) * 32 + tid];
    }
    __syncthreads();

    // P = causal(eQ^T-tile . eK-tile): thread (tq, tk) does 4x4
    int tk = tid & 15, tq = tid >> 4;
    {
        float p[4][4] = {};
        #pragma unroll
        for (int i = 0; i < 32; i++) {
            float4 a4 = *(float4*)&sQ[i][tq * 4];
            float4 b4 = *(float4*)&sK[i][tk * 4];
            float ar[4] = {a4.x, a4.y, a4.z, a4.w};
            float br[4] = {b4.x, b4.y, b4.z, b4.w};
            #pragma unroll
            for (int r = 0; r < 4; r++)
                #pragma unroll
                for (int c = 0; c < 4; c++)
                    p[r][c] += ar[r] * br[c];
        }
        #pragma unroll
        for (int r = 0; r < 4; r++)
            #pragma unroll
            for (int c = 0; c < 4; c++)
                sP[tq * 4 + r][tk * 4 + c] =
                    (tk * 4 + c > tq * 4 + r) ? 0.f : p[r][c];
    }
    __syncthreads();

    // S = eQ@St_prev + P@eV ; Z = eQ@z_prev + rowsum(P)
    int vx = tid & 7, ry = tid >> 3;
    float Sacc[2][4] = {};
    float Zacc[2] = {};
    {
        #pragma unroll 4
        for (int i = 0; i < 32; i++) {
            float q0 = sQ[i][ry * 2 + 0];
            float q1 = sQ[i][ry * 2 + 1];
            float4 st = *(float4*)&sSt[i][vx * 4];
            Sacc[0][0] += q0 * st.x; Sacc[0][1] += q0 * st.y;
            Sacc[0][2] += q0 * st.z; Sacc[0][3] += q0 * st.w;
            Sacc[1][0] += q1 * st.x; Sacc[1][1] += q1 * st.y;
            Sacc[1][2] += q1 * st.z; Sacc[1][3] += q1 * st.w;
            if (vx == 0) {
                float z = sZp[i];
                Zacc[0] += q0 * z; Zacc[1] += q1 * z;
            }
        }
        #pragma unroll 8
        for (int s = 0; s < 64; s++) {
            float p0 = sP[ry * 2 + 0][s];
            float p1 = sP[ry * 2 + 1][s];
            float4 vv = *(float4*)&sV[s][vx * 4];
            Sacc[0][0] += p0 * vv.x; Sacc[0][1] += p0 * vv.y;
            Sacc[0][2] += p0 * vv.z; Sacc[0][3] += p0 * vv.w;
            Sacc[1][0] += p1 * vv.x; Sacc[1][1] += p1 * vv.y;
            Sacc[1][2] += p1 * vv.z; Sacc[1][3] += p1 * vv.w;
            if (vx == 0) { Zacc[0] += p0; Zacc[1] += p1; }
        }
    }
    if (vx == 0) { sZ[ry * 2] = Zacc[0]; sZ[ry * 2 + 1] = Zacc[1]; }
    __syncthreads();
    #pragma unroll
    for (int r = 0; r < 2; r++) {
        int row = t0 + ry * 2 + r;
        float lz = __logf(sZ[ry * 2 + r]);
        float4 o;
        o.x = __logf(Sacc[r][0]) - lz;
        o.y = __logf(Sacc[r][1]) - lz;
        o.z = __logf(Sacc[r][2]) - lz;
        o.w = __logf(Sacc[r][3]) - lz;
        *(float4*)&att[(size_t)row * kD + h * 32 + vx * 4] = o;
    }
}

// ================================================================ launch
extern "C" void kernel_launch(void* const* d_in, const int* in_sizes, int n_in,
                              void* d_out, int out_size) {
    const int*   tok     = (const int*)  d_in[0];
    const float* embed_w = (const float*)d_in[1];
    const float* pos_w   = (const float*)d_in[2];
    const float* pos_b   = (const float*)d_in[3];
    const float* ln1_g   = (const float*)d_in[4];
    const float* ln1_b   = (const float*)d_in[5];
    const float* qkv_w   = (const float*)d_in[6];
    const float* qkv_b   = (const float*)d_in[7];
    const float* ff_w1   = (const float*)d_in[8];
    const float* ff_b1   = (const float*)d_in[9];
    const float* ff_w2   = (const float*)d_in[10];
    const float* lnf_g   = (const float*)d_in[11];
    const float* lnf_b   = (const float*)d_in[12];
    float* out = (float*)d_out;

    float *x, *xn, *hbuf, *y, *att, *g, *st, *zsb;
    cudaGetSymbolAddress((void**)&x,    g_x);
    cudaGetSymbolAddress((void**)&xn,   g_xn);
    cudaGetSymbolAddress((void**)&hbuf, g_h);
    cudaGetSymbolAddress((void**)&y,    g_y);
    cudaGetSymbolAddress((void**)&att,  g_att);
    cudaGetSymbolAddress((void**)&g,    g_g);
    cudaGetSymbolAddress((void**)&st,   g_state);
    cudaGetSymbolAddress((void**)&zsb,  g_zs);

    // 1. embedding
    embed_kernel<<<(kS * kD + 255) / 256, 256>>>(tok, embed_w, x);

    // 2. positional: h = x @ pos_w + pos_b ; scan ; x += rec
    gemm_mma_kernel<false><<<dim3(kFF / 128, kS / 128), 256, kSmemBytes>>>(
        x, pos_w, pos_b, nullptr, hbuf, kFF);
    pos_scan_kernel<<<6, 128>>>(hbuf, x);

    // 3. layers
    for (int l = 0; l < kL; l++) {
        ln_kernel<<<kS, 256>>>(x, ln1_g + (size_t)l * kD, ln1_b + (size_t)l * kD, xn);
        gemm_mma_kernel<false><<<dim3(kQKV / 128, kS / 128), 256, kSmemBytes>>>(
            xn, qkv_w + (size_t)l * kD * kQKV, qkv_b + (size_t)l * kQKV, nullptr, y, kQKV);
        attn_state_kernel<<<dim3(16, kH), 256>>>(y, st, zsb);
        attn_prefix_kernel<<<kH, 1024>>>(st, zsb);
        attn_out_kernel<<<dim3(16, kH), 256>>>(y, st, zsb, att);
        gemm_mma_kernel<false><<<dim3(kFF / 128, kS / 128), 256, kSmemBytes>>>(
            att, ff_w1 + (size_t)l * kD * kFF, ff_b1 + (size_t)l * kFF, nullptr, hbuf, kFF);
        glu_kernel<<<(kS * kD + 255) / 256, 256>>>(hbuf, g);
        gemm_mma_kernel<false><<<dim3(kD / 128, kS / 128), 256, kSmemBytes>>>(
            g, ff_w2 + (size_t)l * kD * kD, nullptr, x, x, kD);
    }

    // 4. final LN + logits (embed_w is [V, K] row-major -> TRANSB path)
    ln_kernel<<<kS, 256>>>(x, lnf_g, lnf_b, xn);
    gemm_mma_kernel<true><<<dim3(kV / 128, kS / 128), 256, kSmemBytes>>>(
        xn, embed_w, nullptr, nullptr, out, kV);
}

// round 9
// speedup vs baseline: 2.5536x; 1.0576x over previous
#include <cuda_runtime.h>
#include <cuda_bf16.h>
#include <math.h>
#include <stdint.h>

// Problem constants
constexpr int kS    = 1024;
constexpr int kD    = 768;
constexpr int kL    = 12;
constexpr int kH    = 24;
constexpr int kQKV  = 2304;   // H*(32+32+32)
constexpr int kFF   = 1536;   // 2*D
constexpr int kV    = 50304;
constexpr int kK    = 768;    // shared GEMM K

// Scratch (device globals; no allocation allowed)
__device__ float g_x    [kS * kD];
__device__ float g_xn   [kS * kD];
__device__ float g_h    [kS * kFF];
__device__ float g_y    [kS * kQKV];
__device__ float g_att  [kS * kD];
__device__ float g_g    [kS * kD];
__device__ float g_state[kH * 16 * 32 * 32];
__device__ float g_zs   [kH * 16 * 32];

// ================================================================ bf16-split mma GEMM
// C[M,N] = A[M,K=768] @ op(B) (+bias) (+addsrc), fp32 in/out.
// Split x = hi + lo (bf16); C = Ahi*Bhi + Ahi*Blo + Alo*Bhi.
// BM=128, BN=64, BK=16, 256 threads (8 warps, 4m x 2n), warp tile 32x32.
// Fragments via ldmatrix.x4; smem row r at word offset r*12 (48B stride:
// 16B-aligned rows, and 3r mod 8 is a permutation -> LDSM conflict-free).
constexpr int kNIter = kK / 16;     // 48
constexpr int kABuf  = 1536;        // words per A buffer
constexpr int kBBuf  = 768;         // words per B buffer
constexpr int SA_HI  = 0;
constexpr int SA_LO  = 2 * kABuf;   // 3072
constexpr int SB_HI  = 4 * kABuf;   // 6144
constexpr int SB_LO  = SB_HI + 2 * kBBuf;  // 7680
constexpr int kSmWords = SB_LO + 2 * kBBuf; // 9216 words = 36 KB

__device__ __forceinline__ int rowbase(int r) { return r * 12; }

__device__ __forceinline__ uint32_t pack_split(float x, float y, float& lx, float& ly) {
    __nv_bfloat162 h = __floats2bfloat162_rn(x, y);
    lx = x - __bfloat162float(h.x);
    ly = y - __bfloat162float(h.y);
    return *reinterpret_cast<uint32_t*>(&h);
}
__device__ __forceinline__ uint32_t pack_bf2(float x, float y) {
    __nv_bfloat162 h = __floats2bfloat162_rn(x, y);
    return *reinterpret_cast<uint32_t*>(&h);
}

__device__ __forceinline__ void mma_bf16(float c[4],
                                         const uint32_t a[4],
                                         const uint32_t b[2]) {
    asm volatile(
        "mma.sync.aligned.m16n8k16.row.col.f32.bf16.bf16.f32 "
        "{%0,%1,%2,%3}, {%4,%5,%6,%7}, {%8,%9}, {%0,%1,%2,%3};"
        : "+f"(c[0]), "+f"(c[1]), "+f"(c[2]), "+f"(c[3])
        : "r"(a[0]), "r"(a[1]), "r"(a[2]), "r"(a[3]),
          "r"(b[0]), "r"(b[1]));
}

__device__ __forceinline__ void ldsm4(uint32_t r[4], uint32_t addr) {
    asm volatile("ldmatrix.sync.aligned.m8n8.x4.shared.b16 {%0,%1,%2,%3}, [%4];"
        : "=r"(r[0]), "=r"(r[1]), "=r"(r[2]), "=r"(r[3]) : "r"(addr));
}

template <bool TRANSB>
__global__ void __launch_bounds__(256, 2)
gemm_mma_kernel(const float* __restrict__ A, const float* __restrict__ B,
                const float* __restrict__ bias, const float* __restrict__ addsrc,
                float* __restrict__ C, int N) {
    __shared__ uint32_t sm[kSmWords];

    int tid  = threadIdx.x;
    int lane = tid & 31;
    int w    = tid >> 5;
    int g    = lane >> 2;
    int t4   = lane & 3;
    int n0   = blockIdx.x * 64;
    int m0   = blockIdx.y * 128;
    int wm   = (w & 3) * 32;
    int wn   = (w >> 2) * 32;

    // ---------- ldmatrix per-lane addresses (loop-invariant word offsets)
    int l8 = lane & 7, quad = lane >> 3;
    int rowA0 = wm + (quad & 1) * 8 + l8;          // f=0 tile rows
    int offA0 = rowbase(rowA0) + (quad >> 1) * 4;
    int rowA1 = rowA0 + 16;                        // f=1
    int offA1 = rowbase(rowA1) + (quad >> 1) * 4;
    int rowB0 = wn + (quad >> 1) * 8 + l8;         // j=0,1 pair
    int offB0 = rowbase(rowB0) + (quad & 1) * 4;
    int rowB2 = rowB0 + 16;                        // j=2,3 pair
    int offB2 = rowbase(rowB2) + (quad & 1) * 4;

    uint32_t su = (uint32_t)__cvta_generic_to_shared(sm);
    uint32_t aHi0 = su + (SA_HI + offA0) * 4, aHi1 = su + (SA_HI + offA1) * 4;
    uint32_t aLo0 = su + (SA_LO + offA0) * 4, aLo1 = su + (SA_LO + offA1) * 4;
    uint32_t bHi0 = su + (SB_HI + offB0) * 4, bHi2 = su + (SB_HI + offB2) * 4;
    uint32_t bLo0 = su + (SB_LO + offB0) * 4, bLo2 = su + (SB_LO + offB2) * 4;

    // ---------- staging maps
    // A: rows srow, srow+64; k floats scol..scol+3
    int srow = tid >> 2;
    int scol = (tid & 3) * 4;
    const float* gA0 = A + (size_t)(m0 + srow) * kK + scol;
    const float* gA1 = A + (size_t)(m0 + srow + 64) * kK + scol;
    int wA0 = rowbase(srow) + (tid & 3) * 2;
    int wA1 = rowbase(srow + 64) + (tid & 3) * 2;

    // B
    const float* gBt = nullptr;   // TRANSB: row rB = tid>>2, chunk tid&3
    const float* gBc = nullptr;   // NN: col n, rows q*4..q*4+3
    int wB;
    int q = tid >> 6, nn = tid & 63;
    if (TRANSB) {
        gBt = B + (size_t)(n0 + srow) * kK + scol;
        wB  = rowbase(srow) + (tid & 3) * 2;
    } else {
        gBc = B + (size_t)(q * 4) * N + n0 + nn;
        wB  = rowbase(nn) + 2 * q;
    }

    float acc[2][4][4];
    #pragma unroll
    for (int f = 0; f < 2; f++)
        #pragma unroll
        for (int j = 0; j < 4; j++)
            #pragma unroll
            for (int u = 0; u < 4; u++) acc[f][j][u] = 0.f;

    float4 ra0, ra1, rb4;
    float rbn[4];

    auto ldg = [&](int it) {
        int k0 = it * 16;
        ra0 = *(const float4*)(gA0 + k0);
        ra1 = *(const float4*)(gA1 + k0);
        if (TRANSB) {
            rb4 = *(const float4*)(gBt + k0);
        } else {
            const float* p = gBc + (size_t)k0 * N;
            #pragma unroll
            for (int u = 0; u < 4; u++) rbn[u] = p[(size_t)u * N];
        }
    };

    auto sts = [&](int buf) {
        int boA = buf * kABuf, boB = buf * kBBuf;
        float l0, l1, l2, l3;
        uint32_t h0 = pack_split(ra0.x, ra0.y, l0, l1);
        uint32_t h1 = pack_split(ra0.z, ra0.w, l2, l3);
        sm[SA_HI + boA + wA0] = h0; sm[SA_HI + boA + wA0 + 1] = h1;
        sm[SA_LO + boA + wA0] = pack_bf2(l0, l1);
        sm[SA_LO + boA + wA0 + 1] = pack_bf2(l2, l3);
        h0 = pack_split(ra1.x, ra1.y, l0, l1);
        h1 = pack_split(ra1.z, ra1.w, l2, l3);
        sm[SA_HI + boA + wA1] = h0; sm[SA_HI + boA + wA1 + 1] = h1;
        sm[SA_LO + boA + wA1] = pack_bf2(l0, l1);
        sm[SA_LO + boA + wA1 + 1] = pack_bf2(l2, l3);
        if (TRANSB) {
            h0 = pack_split(rb4.x, rb4.y, l0, l1);
            h1 = pack_split(rb4.z, rb4.w, l2, l3);
            sm[SB_HI + boB + wB] = h0; sm[SB_HI + boB + wB + 1] = h1;
            sm[SB_LO + boB + wB] = pack_bf2(l0, l1);
            sm[SB_LO + boB + wB + 1] = pack_bf2(l2, l3);
        } else {
            h0 = pack_split(rbn[0], rbn[1], l0, l1);
            h1 = pack_split(rbn[2], rbn[3], l2, l3);
            sm[SB_HI + boB + wB] = h0; sm[SB_HI + boB + wB + 1] = h1;
            sm[SB_LO + boB + wB] = pack_bf2(l0, l1);
            sm[SB_LO + boB + wB + 1] = pack_bf2(l2, l3);
        }
    };

    ldg(0);
    sts(0);
    __syncthreads();

    for (int it = 0; it < kNIter; it++) {
        int buf = it & 1;
        uint32_t oA = (uint32_t)(buf * kABuf * 4);
        uint32_t oB = (uint32_t)(buf * kBBuf * 4);
        if (it + 1 < kNIter) ldg(it + 1);

        uint32_t ah[2][4], al[2][4], bq0[4], bq2[4], lq0[4], lq2[4];
        ldsm4(ah[0], aHi0 + oA);
        ldsm4(ah[1], aHi1 + oA);
        ldsm4(al[0], aLo0 + oA);
        ldsm4(al[1], aLo1 + oA);
        ldsm4(bq0, bHi0 + oB);
        ldsm4(bq2, bHi2 + oB);
        ldsm4(lq0, bLo0 + oB);
        ldsm4(lq2, bLo2 + oB);

        uint32_t bh[4][2] = {{bq0[0], bq0[1]}, {bq0[2], bq0[3]},
                             {bq2[0], bq2[1]}, {bq2[2], bq2[3]}};
        uint32_t bl[4][2] = {{lq0[0], lq0[1]}, {lq0[2], lq0[3]},
                             {lq2[0], lq2[1]}, {lq2[2], lq2[3]}};

        #pragma unroll
        for (int f = 0; f < 2; f++)
            #pragma unroll
            for (int j = 0; j < 4; j++) {
                mma_bf16(acc[f][j], ah[f], bh[j]);
                mma_bf16(acc[f][j], ah[f], bl[j]);
                mma_bf16(acc[f][j], al[f], bh[j]);
            }

        if (it + 1 < kNIter) sts(buf ^ 1);
        __syncthreads();
    }

    // epilogue
    #pragma unroll
    for (int f = 0; f < 2; f++) {
        int r0 = m0 + wm + f * 16 + g;
        #pragma unroll
        for (int j = 0; j < 4; j++) {
            int n = n0 + wn + j * 8 + t4 * 2;
            float2 lo = {acc[f][j][0], acc[f][j][1]};
            float2 hi = {acc[f][j][2], acc[f][j][3]};
            if (bias) {
                float2 b2 = *(const float2*)(bias + n);
                lo.x += b2.x; lo.y += b2.y;
                hi.x += b2.x; hi.y += b2.y;
            }
            size_t o0 = (size_t)r0 * N + n;
            size_t o1 = (size_t)(r0 + 8) * N + n;
            if (addsrc) {
                float2 s0 = *(const float2*)(addsrc + o0);
                float2 s1 = *(const float2*)(addsrc + o1);
                lo.x += s0.x; lo.y += s0.y;
                hi.x += s1.x; hi.y += s1.y;
            }
            *(float2*)(C + o0) = lo;
            *(float2*)(C + o1) = hi;
        }
    }
}

// ================================================================ embed gather (float4)
__global__ void embed_kernel(const int* __restrict__ tok,
                             const float* __restrict__ ew,
                             float* __restrict__ x) {
    int idx = blockIdx.x * blockDim.x + threadIdx.x;
    if (idx < kS * (kD / 4)) {
        int t = idx / 192, d4 = idx - t * 192;
        float4 v = *(const float4*)(ew + (size_t)tok[t] * kD + d4 * 4);
        *(float4*)(x + (size_t)t * kD + d4 * 4) = v;
    }
}

// ================================================================ layernorm
__global__ void ln_kernel(const float* __restrict__ x,
                          const float* __restrict__ gw,
                          const float* __restrict__ bw,
                          float* __restrict__ out) {
    int row = blockIdx.x;
    int tid = threadIdx.x;  // 256
    const float* xr = x + (size_t)row * kD;
    float v0 = xr[tid], v1 = xr[tid + 256], v2 = xr[tid + 512];
    float s = v0 + v1 + v2;
    __shared__ float red[8];
    unsigned lane = tid & 31, wid = tid >> 5;
    #pragma unroll
    for (int o = 16; o > 0; o >>= 1) s += __shfl_down_sync(0xffffffffu, s, o);
    if (lane == 0) red[wid] = s;
    __syncthreads();
    float tot = 0.f;
    #pragma unroll
    for (int i = 0; i < 8; i++) tot += red[i];
    float m = tot * (1.f / 768.f);
    float d0 = v0 - m, d1 = v1 - m, d2 = v2 - m;
    float s2 = d0 * d0 + d1 * d1 + d2 * d2;
    __syncthreads();
    #pragma unroll
    for (int o = 16; o > 0; o >>= 1) s2 += __shfl_down_sync(0xffffffffu, s2, o);
    if (lane == 0) red[wid] = s2;
    __syncthreads();
    float tot2 = 0.f;
    #pragma unroll
    for (int i = 0; i < 8; i++) tot2 += red[i];
    float scale = rsqrtf(tot2 * (1.f / 768.f) + 1e-5f);
    float* orow = out + (size_t)row * kD;
    orow[tid]       = d0 * scale * gw[tid]       + bw[tid];
    orow[tid + 256] = d1 * scale * gw[tid + 256] + bw[tid + 256];
    orow[tid + 512] = d2 * scale * gw[tid + 512] + bw[tid + 512];
}

// ================================================================ pos scan
__global__ void pos_scan_kernel(const float* __restrict__ h, float* __restrict__ x) {
    int d = blockIdx.x * blockDim.x + threadIdx.x;
    if (d >= kD) return;
    float a = 0.f, Lv = 0.f;
    for (int t = 0; t < kS; t++) {
        float hc = h[(size_t)t * kFF + d];
        float hl = h[(size_t)t * kFF + kD + d];
        float lc = fminf(hc, 0.f) - log1pf(__expf(-fabsf(hc)));
        a += lc;
        float v = hl - a;
        float mx = fmaxf(Lv, v), mn = fminf(Lv, v);
        Lv = mx + log1pf(__expf(mn - mx));
        x[(size_t)t * kD + d] += a + Lv;
    }
}

// ================================================================ GLU (float4)
__global__ void glu_kernel(const float* __restrict__ z, float* __restrict__ g) {
    int idx = blockIdx.x * blockDim.x + threadIdx.x;
    if (idx < kS * (kD / 4)) {
        int t = idx / 192, d4 = idx - t * 192;
        float4 a = *(const float4*)(z + (size_t)t * kFF + d4 * 4);
        float4 b = *(const float4*)(z + (size_t)t * kFF + kD + d4 * 4);
        float4 o;
        o.x = a.x / (1.f + __expf(-b.x));
        o.y = a.y / (1.f + __expf(-b.y));
        o.z = a.z / (1.f + __expf(-b.z));
        o.w = a.w / (1.f + __expf(-b.w));
        *(float4*)(g + (size_t)t * kD + d4 * 4) = o;
    }
}

// ================================================================ chunked attention
__global__ void __launch_bounds__(256)
attn_state_kernel(const float* __restrict__ y, float* __restrict__ state,
                  float* __restrict__ zs) {
    __shared__ float sK[64][36];
    __shared__ float sV[64][36];
    int t = blockIdx.x, h = blockIdx.y;
    int tid = threadIdx.x;
    int i4 = (tid & 7) * 4, rr = tid >> 3;
    #pragma unroll
    for (int rep = 0; rep < 2; rep++) {
        int s = rr + rep * 32;
        const float* base = y + (size_t)(t * 64 + s) * kQKV + h * 96;
        float4 kv = *(const float4*)(base + 32 + i4);
        float4 vv = *(const float4*)(base + 64 + i4);
        float4 ek = {__expf(kv.x), __expf(kv.y), __expf(kv.z), __expf(kv.w)};
        float4 ev = {__expf(vv.x), __expf(vv.y), __expf(vv.z), __expf(vv.w)};
        *(float4*)&sK[s][i4] = ek;
        *(float4*)&sV[s][i4] = ev;
    }
    __syncthreads();
    int i = tid >> 3, j0 = (tid & 7) * 4;
    float a0 = 0.f, a1 = 0.f, a2 = 0.f, a3 = 0.f;
    #pragma unroll 4
    for (int s = 0; s < 64; s++) {
        float k = sK[s][i];
        float4 v = *(float4*)&sV[s][j0];
        a0 += k * v.x; a1 += k * v.y; a2 += k * v.z; a3 += k * v.w;
    }
    float4 o = {a0, a1, a2, a3};
    *(float4*)&state[((size_t)(h * 16 + t) * 32 + i) * 32 + j0] = o;
    if (tid < 32) {
        float z = 0.f;
        #pragma unroll 4
        for (int s = 0; s < 64; s++) z += sK[s][tid];
        zs[(h * 16 + t) * 32 + tid] = z;
    }
}

// prefix over 16 tiles (prefetch then scan)
__global__ void __launch_bounds__(1024)
attn_prefix_kernel(float* __restrict__ state, float* __restrict__ zs) {
    int h = blockIdx.x;
    int idx = threadIdx.x;
    float v[16];
    #pragma unroll
    for (int t = 0; t < 16; t++)
        v[t] = state[(size_t)(h * 16 + t) * 1024 + idx];
    float run = 0.f;
    #pragma unroll
    for (int t = 0; t < 16; t++) {
        state[(size_t)(h * 16 + t) * 1024 + idx] = run;
        run += v[t];
    }
    if (idx < 32) {
        float zv[16];
        #pragma unroll
        for (int t = 0; t < 16; t++) zv[t] = zs[(h * 16 + t) * 32 + idx];
        float rz = 0.f;
        #pragma unroll
        for (int t = 0; t < 16; t++) {
            zs[(h * 16 + t) * 32 + idx] = rz;
            rz += zv[t];
        }
    }
}

__global__ void __launch_bounds__(256)
attn_out_kernel(const float* __restrict__ y, const float* __restrict__ state,
                const float* __restrict__ zs, float* __restrict__ att) {
    __shared__ float sQ[32][64];
    __shared__ float sK[32][64];
    __shared__ float sV[64][36];
    __shared__ float sSt[32][36];
    __shared__ float sZp[32];
    __shared__ float sP[64][65];
    __shared__ float sZ[64];

    int qt = blockIdx.x, h = blockIdx.y;
    int t0 = qt * 64;
    int tid = threadIdx.x;
    int i4 = (tid & 7) * 4, rr = tid >> 3;

    #pragma unroll
    for (int rep = 0; rep < 2; rep++) {
        int s = rr + rep * 32;
        const float* base = y + (size_t)(t0 + s) * kQKV + h * 96;
        float4 qv = *(const float4*)(base + i4);
        sQ[i4 + 0][s] = __expf(qv.x); sQ[i4 + 1][s] = __expf(qv.y);
        sQ[i4 + 2][s] = __expf(qv.z); sQ[i4 + 3][s] = __expf(qv.w);
        float4 kv = *(const float4*)(base + 32 + i4);
        sK[i4 + 0][s] = __expf(kv.x); sK[i4 + 1][s] = __expf(kv.y);
        sK[i4 + 2][s] = __expf(kv.z); sK[i4 + 3][s] = __expf(kv.w);
        float4 vv = *(const float4*)(base + 64 + i4);
        float4 ev = {__expf(vv.x), __expf(vv.y), __expf(vv.z), __expf(vv.w)};
        *(float4*)&sV[s][i4] = ev;
    }
    {
        int i = tid >> 3, j0 = (tid & 7) * 4;
        float4 st = *(const float4*)&state[((size_t)(h * 16 + qt) * 32 + i) * 32 + j0];
        *(float4*)&sSt[i][j0] = st;
        if (tid < 32) sZp[tid] = zs[(h * 16 + qt) * 32 + tid];
    }
    __syncthreads();

    int tk = tid & 15, tq = tid >> 4;
    {
        float p[4][4] = {};
        #pragma unroll
        for (int i = 0; i < 32; i++) {
            float4 a4 = *(float4*)&sQ[i][tq * 4];
            float4 b4 = *(float4*)&sK[i][tk * 4];
            float ar[4] = {a4.x, a4.y, a4.z, a4.w};
            float br[4] = {b4.x, b4.y, b4.z, b4.w};
            #pragma unroll
            for (int r = 0; r < 4; r++)
                #pragma unroll
                for (int c = 0; c < 4; c++)
                    p[r][c] += ar[r] * br[c];
        }
        #pragma unroll
        for (int r = 0; r < 4; r++)
            #pragma unroll
            for (int c = 0; c < 4; c++)
                sP[tq * 4 + r][tk * 4 + c] =
                    (tk * 4 + c > tq * 4 + r) ? 0.f : p[r][c];
    }
    __syncthreads();

    int vx = tid & 7, ry = tid >> 3;
    float Sacc[2][4] = {};
    float Zacc[2] = {};
    {
        #pragma unroll 4
        for (int i = 0; i < 32; i++) {
            float q0 = sQ[i][ry * 2 + 0];
            float q1 = sQ[i][ry * 2 + 1];
            float4 st = *(float4*)&sSt[i][vx * 4];
            Sacc[0][0] += q0 * st.x; Sacc[0][1] += q0 * st.y;
            Sacc[0][2] += q0 * st.z; Sacc[0][3] += q0 * st.w;
            Sacc[1][0] += q1 * st.x; Sacc[1][1] += q1 * st.y;
            Sacc[1][2] += q1 * st.z; Sacc[1][3] += q1 * st.w;
            if (vx == 0) {
                float z = sZp[i];
                Zacc[0] += q0 * z; Zacc[1] += q1 * z;
            }
        }
        #pragma unroll 8
        for (int s = 0; s < 64; s++) {
            float p0 = sP[ry * 2 + 0][s];
            float p1 = sP[ry * 2 + 1][s];
            float4 vv = *(float4*)&sV[s][vx * 4];
            Sacc[0][0] += p0 * vv.x; Sacc[0][1] += p0 * vv.y;
            Sacc[0][2] += p0 * vv.z; Sacc[0][3] += p0 * vv.w;
            Sacc[1][0] += p1 * vv.x; Sacc[1][1] += p1 * vv.y;
            Sacc[1][2] += p1 * vv.z; Sacc[1][3] += p1 * vv.w;
            if (vx == 0) { Zacc[0] += p0; Zacc[1] += p1; }
        }
    }
    if (vx == 0) { sZ[ry * 2] = Zacc[0]; sZ[ry * 2 + 1] = Zacc[1]; }
    __syncthreads();
    #pragma unroll
    for (int r = 0; r < 2; r++) {
        int row = t0 + ry * 2 + r;
        float lz = __logf(sZ[ry * 2 + r]);
        float4 o;
        o.x = __logf(Sacc[r][0]) - lz;
        o.y = __logf(Sacc[r][1]) - lz;
        o.z = __logf(Sacc[r][2]) - lz;
        o.w = __logf(Sacc[r][3]) - lz;
        *(float4*)&att[(size_t)row * kD + h * 32 + vx * 4] = o;
    }
}

// ================================================================ launch
extern "C" void kernel_launch(void* const* d_in, const int* in_sizes, int n_in,
                              void* d_out, int out_size) {
    const int*   tok     = (const int*)  d_in[0];
    const float* embed_w = (const float*)d_in[1];
    const float* pos_w   = (const float*)d_in[2];
    const float* pos_b   = (const float*)d_in[3];
    const float* ln1_g   = (const float*)d_in[4];
    const float* ln1_b   = (const float*)d_in[5];
    const float* qkv_w   = (const float*)d_in[6];
    const float* qkv_b   = (const float*)d_in[7];
    const float* ff_w1   = (const float*)d_in[8];
    const float* ff_b1   = (const float*)d_in[9];
    const float* ff_w2   = (const float*)d_in[10];
    const float* lnf_g   = (const float*)d_in[11];
    const float* lnf_b   = (const float*)d_in[12];
    float* out = (float*)d_out;

    float *x, *xn, *hbuf, *y, *att, *g, *st, *zsb;
    cudaGetSymbolAddress((void**)&x,    g_x);
    cudaGetSymbolAddress((void**)&xn,   g_xn);
    cudaGetSymbolAddress((void**)&hbuf, g_h);
    cudaGetSymbolAddress((void**)&y,    g_y);
    cudaGetSymbolAddress((void**)&att,  g_att);
    cudaGetSymbolAddress((void**)&g,    g_g);
    cudaGetSymbolAddress((void**)&st,   g_state);
    cudaGetSymbolAddress((void**)&zsb,  g_zs);

    // 1. embedding
    embed_kernel<<<(kS * 192 + 255) / 256, 256>>>(tok, embed_w, x);

    // 2. positional
    gemm_mma_kernel<false><<<dim3(kFF / 64, kS / 128), 256>>>(
        x, pos_w, pos_b, nullptr, hbuf, kFF);
    pos_scan_kernel<<<6, 128>>>(hbuf, x);

    // 3. layers
    for (int l = 0; l < kL; l++) {
        ln_kernel<<<kS, 256>>>(x, ln1_g + (size_t)l * kD, ln1_b + (size_t)l * kD, xn);
        gemm_mma_kernel<false><<<dim3(kQKV / 64, kS / 128), 256>>>(
            xn, qkv_w + (size_t)l * kD * kQKV, qkv_b + (size_t)l * kQKV, nullptr, y, kQKV);
        attn_state_kernel<<<dim3(16, kH), 256>>>(y, st, zsb);
        attn_prefix_kernel<<<kH, 1024>>>(st, zsb);
        attn_out_kernel<<<dim3(16, kH), 256>>>(y, st, zsb, att);
        gemm_mma_kernel<false><<<dim3(kFF / 64, kS / 128), 256>>>(
            att, ff_w1 + (size_t)l * kD * kFF, ff_b1 + (size_t)l * kFF, nullptr, hbuf, kFF);
        glu_kernel<<<(kS * 192 + 255) / 256, 256>>>(hbuf, g);
        gemm_mma_kernel<false><<<dim3(kD / 64, kS / 128), 256>>>(
            g, ff_w2 + (size_t)l * kD * kD, nullptr, x, x, kD);
    }

    // 4. final LN + logits
    ln_kernel<<<kS, 256>>>(x, lnf_g, lnf_b, xn);
    gemm_mma_kernel<true><<<dim3(kV / 64, kS / 128), 256>>>(
        xn, embed_w, nullptr, nullptr, out, kV);
}